// round 11
// baseline (speedup 1.0000x reference)
#include <cuda_runtime.h>
#include <cuda_fp16.h>
#include <cstdint>

#define H 768
#define BATCHN 128
#define NCHUNK 4
#define CHUNK_B (BATCHN / NCHUNK)   // 32
#define TM 128
#define TKC 32
#define NCT (H / 32)            // 24 k-tiles (ct), task ct has ct+1 j-steps
#define NXB (6 * NCT)           // 144 tasks per batch
#define NTHREADS 256

// SMEM per stage: h 128 rows + l 128 rows + Vh 32 + Vl 32, 80B pitch
#define ROWB 80
#define OFF_H  0
#define OFF_L  (128 * ROWB)               // 10240
#define OFF_VH (2 * 128 * ROWB)           // 20480
#define OFF_VL (OFF_VH + 32 * ROWB)       // 23040
#define STAGE_B (OFF_VL + 32 * ROWB)      // 25600
#define NSTAGE 3
#define OFF_SP (NSTAGE * STAGE_B)         // 76800; partials 2*128 floats
#define SMEM_TOTAL (OFF_SP + 2 * 128 * 4) // 77824 -> 2 CTAs/SM

__device__ float g_logits[BATCHN * H];
__device__ __half g_sh[(size_t)BATCHN * H * H];   // V hi (strict lower + half diag)
__device__ __half g_sl[(size_t)BATCHN * H * H];   // V lo
__device__ __half g_op_hi[H * H];
__device__ __half g_op_lo[H * H];

// ---------------- helpers ----------------
__device__ __forceinline__ uint32_t smem_u32(const void* p) {
    uint32_t a;
    asm("{ .reg .u64 t; cvta.to.shared.u64 t, %1; cvt.u32.u64 %0, t; }" : "=r"(a) : "l"(p));
    return a;
}
__device__ __forceinline__ void ldsm4(uint32_t* r, uint32_t addr) {
    asm volatile("ldmatrix.sync.aligned.m8n8.x4.shared.b16 {%0,%1,%2,%3}, [%4];"
                 : "=r"(r[0]), "=r"(r[1]), "=r"(r[2]), "=r"(r[3]) : "r"(addr));
}
__device__ __forceinline__ void mma16816(float* d, const uint32_t* a, const uint32_t* b) {
    asm volatile(
        "mma.sync.aligned.m16n8k16.row.col.f32.f16.f16.f32 "
        "{%0,%1,%2,%3}, {%4,%5,%6,%7}, {%8,%9}, {%0,%1,%2,%3};"
        : "+f"(d[0]), "+f"(d[1]), "+f"(d[2]), "+f"(d[3])
        : "r"(a[0]), "r"(a[1]), "r"(a[2]), "r"(a[3]), "r"(b[0]), "r"(b[1]));
}
__device__ __forceinline__ void mma16816h(uint32_t* d, const uint32_t* a, const uint32_t* b) {
    asm volatile(
        "mma.sync.aligned.m16n8k16.row.col.f16.f16.f16.f16 "
        "{%0,%1}, {%2,%3,%4,%5}, {%6,%7}, {%0,%1};"
        : "+r"(d[0]), "+r"(d[1])
        : "r"(a[0]), "r"(a[1]), "r"(a[2]), "r"(a[3]), "r"(b[0]), "r"(b[1]));
}
__device__ __forceinline__ void cp16(uint32_t dst, const void* src) {
    asm volatile("cp.async.cg.shared.global [%0], [%1], 16;" :: "r"(dst), "l"(src));
}
__device__ __forceinline__ void cp_commit() { asm volatile("cp.async.commit_group;" ::: "memory"); }
__device__ __forceinline__ void cp_wait1()  { asm volatile("cp.async.wait_group 1;" ::: "memory"); }
__device__ __forceinline__ void cp_wait0()  { asm volatile("cp.async.wait_group 0;" ::: "memory"); }
__device__ __forceinline__ uint32_t pack2(__half a, __half b) {
    __half2 h = __halves2half2(a, b);
    return *reinterpret_cast<uint32_t*>(&h);
}
__device__ __forceinline__ void split2(float s0, float s1, uint32_t& hi, uint32_t& lo) {
    __half h0 = __float2half_rn(s0), h1 = __float2half_rn(s1);
    __half l0 = __float2half_rn(s0 - __half2float(h0));
    __half l1 = __float2half_rn(s1 - __half2float(h1));
    hi = pack2(h0, h1);
    lo = pack2(l0, l1);
}

// ---------------- sym: V[k,j] = sym(A)[k,j] for j<k, V[k,k]=A[k,k]/2, 0 above ----
// grid (24, 24, CHUNK_B): x = Ct (j-tile), y = Rt (k-tile). Only Ct <= Rt active.
__global__ void __launch_bounds__(256)
Measurement_68307159875839_sym(const float* __restrict__ A, int b0) {
    const int Ct = blockIdx.x, Rt = blockIdx.y;
    if (Ct > Rt) return;
    __shared__ float sKJ[32][33], sJK[32][33];
    const int b = b0 + blockIdx.z;
    const float* Ab = A + (size_t)b * H * H;
    __half* vh = g_sh + (size_t)b * H * H;
    __half* vl = g_sl + (size_t)b * H * H;
    const int t = threadIdx.x;
    const int k0 = Rt * 32, j0 = Ct * 32;
    {
        const int r = t >> 3, q = t & 7;
        float4 va = *reinterpret_cast<const float4*>(Ab + (size_t)(k0 + r) * H + j0 + q * 4);
        sKJ[r][q * 4 + 0] = va.x; sKJ[r][q * 4 + 1] = va.y;
        sKJ[r][q * 4 + 2] = va.z; sKJ[r][q * 4 + 3] = va.w;
        float4 vb = *reinterpret_cast<const float4*>(Ab + (size_t)(j0 + r) * H + k0 + q * 4);
        sJK[r][q * 4 + 0] = vb.x; sJK[r][q * 4 + 1] = vb.y;
        sJK[r][q * 4 + 2] = vb.z; sJK[r][q * 4 + 3] = vb.w;
    }
    __syncthreads();
    const int r16 = t >> 4, cp = t & 15;
#pragma unroll
    for (int rr = 0; rr < 2; rr++) {
        const int row = rr * 16 + r16;                 // k-index within tile
        const int c0 = 2 * cp, c1 = 2 * cp + 1;        // j-indices within tile
        float v0 = 0.5f * (sKJ[row][c0] + sJK[c0][row]);
        float v1 = 0.5f * (sKJ[row][c1] + sJK[c1][row]);
        if (Rt == Ct) {
            v0 = (c0 < row) ? v0 : ((c0 == row) ? 0.5f * v0 : 0.f);
            v1 = (c1 < row) ? v1 : ((c1 == row) ? 0.5f * v1 : 0.f);
        }
        uint32_t hi, lo;
        split2(v0, v1, hi, lo);
        size_t off = (size_t)(k0 + row) * H + j0 + c0;
        *reinterpret_cast<uint32_t*>(vh + off) = hi;
        *reinterpret_cast<uint32_t*>(vl + off) = lo;
    }
}

// ---------------- cvt: op fp32 -> fp16 hi/lo, + zero logits ----------------
__global__ void Measurement_68307159875839_cvt(const float* __restrict__ src,
                                               __half* __restrict__ dst_hi,
                                               __half* __restrict__ dst_lo, int n4) {
    int idx = blockIdx.x * blockDim.x + threadIdx.x;
    if (idx < BATCHN * H) g_logits[idx] = 0.0f;
    if (idx >= n4) return;
    float4 v = reinterpret_cast<const float4*>(src)[idx];
    uint32_t h0, l0, h1, l1;
    split2(v.x, v.y, h0, l0);
    split2(v.z, v.w, h1, l1);
    reinterpret_cast<uint2*>(dst_hi)[idx] = make_uint2(h0, h1);
    reinterpret_cast<uint2*>(dst_lo)[idx] = make_uint2(l0, l1);
}

// ---------------- triangular GEMM (3 products) + fused diag ----------------
// G[i,k] = sum_{j<=k} (h+l)[i,j] * (Vh+Vl)[k,j];  logits_i += 2*sum_k G[i,k]*op[i,k]
// per stage: h 512 chunks + l 512 + Vh 128 + Vl 128 = 1280 chunks of 16B
__device__ __forceinline__ void fill_stage(uint32_t smem_base, int t, int i0, int n0,
                                           size_t s_off, int tid) {
    const int k0 = t * TKC;
    const int s = t % NSTAGE;
#pragma unroll
    for (int r = 0; r < 5; r++) {
        int q = r * NTHREADS + tid;
        const __half* src;
        uint32_t off;
        if (q < 512) {
            int row = q >> 2, c = q & 3;
            off = OFF_H + row * ROWB + c * 16;
            src = g_op_hi + (size_t)(i0 + row) * H + k0 + c * 8;
        } else if (q < 1024) {
            int q2 = q - 512, row = q2 >> 2, c = q2 & 3;
            off = OFF_L + row * ROWB + c * 16;
            src = g_op_lo + (size_t)(i0 + row) * H + k0 + c * 8;
        } else if (q < 1152) {
            int q2 = q - 1024, row = q2 >> 2, c = q2 & 3;
            off = OFF_VH + row * ROWB + c * 16;
            src = g_sh + s_off + (size_t)(n0 + row) * H + k0 + c * 8;
        } else {
            int q2 = q - 1152, row = q2 >> 2, c = q2 & 3;
            off = OFF_VL + row * ROWB + c * 16;
            src = g_sl + s_off + (size_t)(n0 + row) * H + k0 + c * 8;
        }
        cp16(smem_base + (uint32_t)(s * STAGE_B) + off, src);
    }
}

// grid: (144, CHUNK_B); x -> (ct descending, i-tile); y = batch-in-chunk.
// 8 warps: 4 M-warps x 2 N-warps; warp tile 32x16.
__global__ void __launch_bounds__(NTHREADS, 2)
Measurement_68307159875839_gemm(const float* __restrict__ op, int b0) {
    extern __shared__ __align__(16) char smem[];
    const uint32_t smem_base = smem_u32(smem);
    const int tid = threadIdx.x;
    const int lane = tid & 31;
    const int w = tid >> 5;
    const int mw = w >> 1;          // 4 M-warps: 32 rows each
    const int nw = w & 1;           // 2 N-warps: 16 cols each
    const int ct = (NCT - 1) - (blockIdx.x / 6);   // big tasks first
    const int i0 = (blockIdx.x % 6) * TM;
    const int NTc = ct + 1;
    const int n0 = ct * 32;
    const int b = b0 + blockIdx.y;
    const size_t s_off = (size_t)b * H * H;

    const uint32_t a_off = (uint32_t)((mw * 32 + (lane & 15)) * ROWB + (lane >> 4) * 16);
    const uint32_t b_off = (uint32_t)((nw * 16 + (lane & 7) + ((lane & 16) >> 1)) * ROWB +
                                      ((lane >> 3) & 1) * 16);

    float accG1[2][2][4];
    uint32_t accG2[2][2][2], accG3[2][2][2];
#pragma unroll
    for (int mt = 0; mt < 2; mt++)
#pragma unroll
        for (int nt = 0; nt < 2; nt++) {
#pragma unroll
            for (int e = 0; e < 4; e++) accG1[mt][nt][e] = 0.f;
            accG2[mt][nt][0] = 0u; accG2[mt][nt][1] = 0u;
            accG3[mt][nt][0] = 0u; accG3[mt][nt][1] = 0u;
        }

    fill_stage(smem_base, 0, i0, n0, s_off, tid); cp_commit();
    if (NTc > 1) { fill_stage(smem_base, 1, i0, n0, s_off, tid); cp_commit(); }

    for (int t = 0; t < NTc; ++t) {
        if (t + 1 < NTc) cp_wait1(); else cp_wait0();
        __syncthreads();

        const uint32_t sb = smem_base + (uint32_t)((t % NSTAGE) * STAGE_B);
#pragma unroll
        for (int k16 = 0; k16 < 2; k16++) {
            const uint32_t kofs = (uint32_t)(k16 * 32);
            uint32_t ah[2][4], al[2][4];
#pragma unroll
            for (int mt = 0; mt < 2; mt++) {
                ldsm4(ah[mt], sb + OFF_H + a_off + mt * 16 * ROWB + kofs);
                ldsm4(al[mt], sb + OFF_L + a_off + mt * 16 * ROWB + kofs);
            }
            uint32_t bvh[4], bvl[4];
            ldsm4(bvh, sb + OFF_VH + b_off + kofs);
            ldsm4(bvl, sb + OFF_VL + b_off + kofs);
#pragma unroll
            for (int mt = 0; mt < 2; mt++)
#pragma unroll
                for (int nt = 0; nt < 2; nt++)
                    mma16816(accG1[mt][nt], ah[mt], &bvh[nt * 2]);
#pragma unroll
            for (int mt = 0; mt < 2; mt++)
#pragma unroll
                for (int nt = 0; nt < 2; nt++)
                    mma16816h(accG2[mt][nt], ah[mt], &bvl[nt * 2]);
#pragma unroll
            for (int mt = 0; mt < 2; mt++)
#pragma unroll
                for (int nt = 0; nt < 2; nt++)
                    mma16816h(accG3[mt][nt], al[mt], &bvh[nt * 2]);
        }
        if (t + 2 < NTc) { fill_stage(smem_base, t + 2, i0, n0, s_off, tid); cp_commit(); }
        else __syncthreads();   // protect smem reuse across stages at the tail
    }

    // epilogue: s_i = sum_k (G1+G2+G3)[i,k] * op[i,k]  (op exact fp32)
    float part[2][2];
#pragma unroll
    for (int mt = 0; mt < 2; mt++)
#pragma unroll
        for (int ir = 0; ir < 2; ir++) {
            const int i_g = i0 + mw * 32 + mt * 16 + (lane >> 2) + ir * 8;
            const size_t base = (size_t)i_g * H + n0 + nw * 16 + (lane & 3) * 2;
            float s = 0.f;
#pragma unroll
            for (int nt = 0; nt < 2; nt++) {
                float2 w2 = *reinterpret_cast<const float2*>(op + base + nt * 8);
                float2 g2 = __half22float2(*reinterpret_cast<__half2*>(&accG2[mt][nt][ir]));
                float2 g3 = __half22float2(*reinterpret_cast<__half2*>(&accG3[mt][nt][ir]));
                s += (accG1[mt][nt][ir * 2 + 0] + g2.x + g3.x) * w2.x
                   + (accG1[mt][nt][ir * 2 + 1] + g2.y + g3.y) * w2.y;
            }
            float v = s;
            v += __shfl_xor_sync(0xffffffffu, v, 1);
            v += __shfl_xor_sync(0xffffffffu, v, 2);
            part[mt][ir] = v;
        }
    float* sp = reinterpret_cast<float*>(smem + OFF_SP);
    if ((lane & 3) == 0) {
#pragma unroll
        for (int mt = 0; mt < 2; mt++)
#pragma unroll
            for (int ir = 0; ir < 2; ir++) {
                int i_loc = mw * 32 + mt * 16 + (lane >> 2) + ir * 8;
                sp[nw * 128 + i_loc] = part[mt][ir];
            }
    }
    __syncthreads();
    for (int i = tid; i < TM; i += NTHREADS)
        atomicAdd(&g_logits[b * H + i0 + i], 2.0f * (sp[i] + sp[128 + i]));
}

// ---------------- softmax ----------------
__global__ void Measurement_68307159875839_softmax(float* __restrict__ out) {
    __shared__ float red[NTHREADS / 32];
    const int b = blockIdx.x, tid = threadIdx.x;
    const float* row = g_logits + b * H;
    float m = -1e30f;
    for (int i = tid; i < H; i += NTHREADS) m = fmaxf(m, row[i]);
#pragma unroll
    for (int o = 16; o > 0; o >>= 1) m = fmaxf(m, __shfl_xor_sync(0xffffffffu, m, o));
    if ((tid & 31) == 0) red[tid >> 5] = m;
    __syncthreads();
    m = red[0];
#pragma unroll
    for (int wv = 1; wv < NTHREADS / 32; wv++) m = fmaxf(m, red[wv]);
    __syncthreads();
    float s = 0.0f;
    for (int i = tid; i < H; i += NTHREADS) s += __expf(row[i] - m);
#pragma unroll
    for (int o = 16; o > 0; o >>= 1) s += __shfl_xor_sync(0xffffffffu, s, o);
    if ((tid & 31) == 0) red[tid >> 5] = s;
    __syncthreads();
    s = 0.0f;
#pragma unroll
    for (int wv = 0; wv < NTHREADS / 32; wv++) s += red[wv];
    const float inv = 1.0f / s;
    for (int i = tid; i < H; i += NTHREADS) out[b * H + i] = __expf(row[i] - m) * inv;
}

extern "C" void kernel_launch(void* const* d_in, const int* in_sizes, int n_in,
                              void* d_out, int out_size) {
    const float* inputs = (const float*)d_in[0];   // [128, 768, 768] fp32
    const float* op     = (const float*)d_in[1];   // [768, 768] fp32
    float* out = (float*)d_out;                    // [128, 768] fp32

    static int configured = 0;
    static cudaStream_t s2;
    static cudaEvent_t evFork;
    static cudaEvent_t evSym[NCHUNK];
    if (!configured) {
        cudaFuncSetAttribute(Measurement_68307159875839_gemm,
                             cudaFuncAttributeMaxDynamicSharedMemorySize, SMEM_TOTAL);
        cudaStreamCreateWithFlags(&s2, cudaStreamNonBlocking);
        cudaEventCreateWithFlags(&evFork, cudaEventDisableTiming);
        for (int c = 0; c < NCHUNK; c++)
            cudaEventCreateWithFlags(&evSym[c], cudaEventDisableTiming);
        configured = 1;
    }
    __half *op_hi, *op_lo;
    cudaGetSymbolAddress((void**)&op_hi, g_op_hi);
    cudaGetSymbolAddress((void**)&op_lo, g_op_lo);

    cudaEventRecord(evFork, 0);
    cudaStreamWaitEvent(s2, evFork, 0);

    const int n4_op = H * H / 4;
    Measurement_68307159875839_cvt<<<(n4_op + 255) / 256, 256>>>(op, op_hi, op_lo, n4_op);

    for (int c = 0; c < NCHUNK; c++) {
        Measurement_68307159875839_sym<<<dim3(NCT, NCT, CHUNK_B), 256, 0, s2>>>(
            inputs, c * CHUNK_B);
        cudaEventRecord(evSym[c], s2);
    }
    for (int c = 0; c < NCHUNK; c++) {
        cudaStreamWaitEvent(0, evSym[c], 0);
        Measurement_68307159875839_gemm<<<dim3(NXB, CHUNK_B), NTHREADS, SMEM_TOTAL>>>(
            op, c * CHUNK_B);
    }
    Measurement_68307159875839_softmax<<<BATCHN, NTHREADS>>>(out);
}

// round 12
// speedup vs baseline: 1.4652x; 1.4652x over previous
#include <cuda_runtime.h>
#include <cuda_fp16.h>
#include <cstdint>

#define H 768
#define BATCHN 128
#define NCHUNK 4
#define CHUNK_B (BATCHN / NCHUNK)   // 32
#define TM 128
#define TNO 64
#define TKC 32
#define NPAIR 6                  // ct pairs (p, 11-p), 26 steps each
#define NXB (6 * NPAIR)          // 36 tasks per batch
#define NTT 26
#define NTHREADS 256

// SMEM per stage: h 128 rows + l 128 rows + Vh 64 + Vl 64; 80B pitch
#define ROWB 80
#define OFF_H  0
#define OFF_L  (128 * ROWB)               // 10240
#define OFF_VH (256 * ROWB)               // 20480
#define OFF_VL (320 * ROWB)               // 25600
#define STAGE_B (384 * ROWB)              // 30720
#define NSTAGE 3
#define OFF_SP (NSTAGE * STAGE_B)         // 92160; partials 2*128 floats
#define SMEM_TOTAL (OFF_SP + 2 * 128 * 4) // 93184 -> 2 CTAs/SM (186368 < 227KB)

__device__ float g_logits[BATCHN * H];
__device__ __half g_sh[(size_t)BATCHN * H * H];   // V hi (lower tri, half diag)
__device__ __half g_sl[(size_t)BATCHN * H * H];   // V lo
__device__ __half g_op_hi[H * H];
__device__ __half g_op_lo[H * H];

// ---------------- helpers ----------------
__device__ __forceinline__ uint32_t smem_u32(const void* p) {
    uint32_t a;
    asm("{ .reg .u64 t; cvta.to.shared.u64 t, %1; cvt.u32.u64 %0, t; }" : "=r"(a) : "l"(p));
    return a;
}
__device__ __forceinline__ void ldsm4(uint32_t* r, uint32_t addr) {
    asm volatile("ldmatrix.sync.aligned.m8n8.x4.shared.b16 {%0,%1,%2,%3}, [%4];"
                 : "=r"(r[0]), "=r"(r[1]), "=r"(r[2]), "=r"(r[3]) : "r"(addr));
}
__device__ __forceinline__ void mma16816(float* d, const uint32_t* a, const uint32_t* b) {
    asm volatile(
        "mma.sync.aligned.m16n8k16.row.col.f32.f16.f16.f32 "
        "{%0,%1,%2,%3}, {%4,%5,%6,%7}, {%8,%9}, {%0,%1,%2,%3};"
        : "+f"(d[0]), "+f"(d[1]), "+f"(d[2]), "+f"(d[3])
        : "r"(a[0]), "r"(a[1]), "r"(a[2]), "r"(a[3]), "r"(b[0]), "r"(b[1]));
}
__device__ __forceinline__ void mma16816h(uint32_t* d, const uint32_t* a, const uint32_t* b) {
    asm volatile(
        "mma.sync.aligned.m16n8k16.row.col.f16.f16.f16.f16 "
        "{%0,%1}, {%2,%3,%4,%5}, {%6,%7}, {%0,%1};"
        : "+r"(d[0]), "+r"(d[1])
        : "r"(a[0]), "r"(a[1]), "r"(a[2]), "r"(a[3]), "r"(b[0]), "r"(b[1]));
}
__device__ __forceinline__ void cp16(uint32_t dst, const void* src) {
    asm volatile("cp.async.cg.shared.global [%0], [%1], 16;" :: "r"(dst), "l"(src));
}
__device__ __forceinline__ void cp_commit() { asm volatile("cp.async.commit_group;" ::: "memory"); }
__device__ __forceinline__ void cp_wait1()  { asm volatile("cp.async.wait_group 1;" ::: "memory"); }
__device__ __forceinline__ void cp_wait0()  { asm volatile("cp.async.wait_group 0;" ::: "memory"); }
__device__ __forceinline__ uint32_t pack2(__half a, __half b) {
    __half2 h = __halves2half2(a, b);
    return *reinterpret_cast<uint32_t*>(&h);
}
__device__ __forceinline__ void split2(float s0, float s1, uint32_t& hi, uint32_t& lo) {
    __half h0 = __float2half_rn(s0), h1 = __float2half_rn(s1);
    __half l0 = __float2half_rn(s0 - __half2float(h0));
    __half l1 = __float2half_rn(s1 - __half2float(h1));
    hi = pack2(h0, h1);
    lo = pack2(l0, l1);
}

// -------- sym: V[k,j] = sym(A)[k,j] j<k, V[k,k]=A[k,k]/2, zero above; also zero
//          the (Rt even, Ct=Rt+1) tiles read by the 64-wide k-blocks. ----------
__global__ void __launch_bounds__(256)
Measurement_68307159875839_sym(const float* __restrict__ A, int b0) {
    const int Ct = blockIdx.x, Rt = blockIdx.y;
    const bool zero_tile = (Ct == Rt + 1) && ((Rt & 1) == 0);
    if (Ct > Rt && !zero_tile) return;
    const int b = b0 + blockIdx.z;
    __half* vh = g_sh + (size_t)b * H * H;
    __half* vl = g_sl + (size_t)b * H * H;
    const int t = threadIdx.x;
    const int k0 = Rt * 32, j0 = Ct * 32;
    const int r16 = t >> 4, cp = t & 15;
    if (zero_tile) {
#pragma unroll
        for (int rr = 0; rr < 2; rr++) {
            size_t off = (size_t)(k0 + rr * 16 + r16) * H + j0 + 2 * cp;
            *reinterpret_cast<uint32_t*>(vh + off) = 0u;
            *reinterpret_cast<uint32_t*>(vl + off) = 0u;
        }
        return;
    }
    __shared__ float sKJ[32][33], sJK[32][33];
    const float* Ab = A + (size_t)b * H * H;
    {
        const int r = t >> 3, q = t & 7;
        float4 va = *reinterpret_cast<const float4*>(Ab + (size_t)(k0 + r) * H + j0 + q * 4);
        sKJ[r][q * 4 + 0] = va.x; sKJ[r][q * 4 + 1] = va.y;
        sKJ[r][q * 4 + 2] = va.z; sKJ[r][q * 4 + 3] = va.w;
        float4 vb = *reinterpret_cast<const float4*>(Ab + (size_t)(j0 + r) * H + k0 + q * 4);
        sJK[r][q * 4 + 0] = vb.x; sJK[r][q * 4 + 1] = vb.y;
        sJK[r][q * 4 + 2] = vb.z; sJK[r][q * 4 + 3] = vb.w;
    }
    __syncthreads();
#pragma unroll
    for (int rr = 0; rr < 2; rr++) {
        const int row = rr * 16 + r16;                 // k within tile
        const int c0 = 2 * cp, c1 = 2 * cp + 1;        // j within tile
        float v0 = 0.5f * (sKJ[row][c0] + sJK[c0][row]);
        float v1 = 0.5f * (sKJ[row][c1] + sJK[c1][row]);
        if (Rt == Ct) {
            v0 = (c0 < row) ? v0 : ((c0 == row) ? 0.5f * v0 : 0.f);
            v1 = (c1 < row) ? v1 : ((c1 == row) ? 0.5f * v1 : 0.f);
        }
        uint32_t hi, lo;
        split2(v0, v1, hi, lo);
        size_t off = (size_t)(k0 + row) * H + j0 + c0;
        *reinterpret_cast<uint32_t*>(vh + off) = hi;
        *reinterpret_cast<uint32_t*>(vl + off) = lo;
    }
}

// ---------------- cvt: op fp32 -> fp16 hi/lo, + zero logits ----------------
__global__ void Measurement_68307159875839_cvt(const float* __restrict__ src,
                                               __half* __restrict__ dst_hi,
                                               __half* __restrict__ dst_lo, int n4) {
    int idx = blockIdx.x * blockDim.x + threadIdx.x;
    if (idx < BATCHN * H) g_logits[idx] = 0.0f;
    if (idx >= n4) return;
    float4 v = reinterpret_cast<const float4*>(src)[idx];
    uint32_t h0, l0, h1, l1;
    split2(v.x, v.y, h0, l0);
    split2(v.z, v.w, h1, l1);
    reinterpret_cast<uint2*>(dst_hi)[idx] = make_uint2(h0, h1);
    reinterpret_cast<uint2*>(dst_lo)[idx] = make_uint2(l0, l1);
}

// ---------------- block-triangular GEMM (3 products) + fused diag ----------------
// per stage: h 512 + l 512 + Vh 256 + Vl 256 = 1536 chunks of 16B -> 6/thread
__device__ __forceinline__ void fill_stage(uint32_t smem_base, int t, int i0,
                                           int NT_a, int n0a, int n0b,
                                           size_t s_off, int tid) {
    const int n0 = (t < NT_a) ? n0a : n0b;
    const int k0 = ((t < NT_a) ? t : (t - NT_a)) * TKC;
    const int s = t % NSTAGE;
#pragma unroll
    for (int r = 0; r < 6; r++) {
        int q = r * NTHREADS + tid;
        const __half* src;
        uint32_t off;
        if (q < 512) {
            int row = q >> 2, c = q & 3;
            off = OFF_H + row * ROWB + c * 16;
            src = g_op_hi + (size_t)(i0 + row) * H + k0 + c * 8;
        } else if (q < 1024) {
            int q2 = q - 512, row = q2 >> 2, c = q2 & 3;
            off = OFF_L + row * ROWB + c * 16;
            src = g_op_lo + (size_t)(i0 + row) * H + k0 + c * 8;
        } else if (q < 1280) {
            int q2 = q - 1024, row = q2 >> 2, c = q2 & 3;
            off = OFF_VH + row * ROWB + c * 16;
            src = g_sh + s_off + (size_t)(n0 + row) * H + k0 + c * 8;
        } else {
            int q2 = q - 1280, row = q2 >> 2, c = q2 & 3;
            off = OFF_VL + row * ROWB + c * 16;
            src = g_sl + s_off + (size_t)(n0 + row) * H + k0 + c * 8;
        }
        cp16(smem_base + (uint32_t)(s * STAGE_B) + off, src);
    }
}

// grid: (36, CHUNK_B); x = i-tile (6) x pair (6); 26 steps per CTA.
// 8 warps: 4 M-warps x 2 N-warps; warp tile 32x32.
__global__ void __launch_bounds__(NTHREADS, 2)
Measurement_68307159875839_gemm(const float* __restrict__ op, int b0) {
    extern __shared__ __align__(16) char smem[];
    const uint32_t smem_base = smem_u32(smem);
    const int tid = threadIdx.x;
    const int lane = tid & 31;
    const int w = tid >> 5;
    const int mw = w >> 1;          // 4 M-warps: 32 rows
    const int nw = w & 1;           // 2 N-warps: 32 cols
    const int i0 = (blockIdx.x % 6) * TM;
    const int p = blockIdx.x / 6;
    const int ct_a = p, ct_b = 11 - p;
    const int NT_a = 2 * (ct_a + 1);
    const int n0a = ct_a * TNO, n0b = ct_b * TNO;
    const int b = b0 + blockIdx.y;
    const size_t s_off = (size_t)b * H * H;

    const uint32_t a_off = (uint32_t)((mw * 32 + (lane & 15)) * ROWB + (lane >> 4) * 16);
    const uint32_t b_row = (uint32_t)(nw * 32 + (lane & 7) + ((lane & 16) >> 1));
    const uint32_t b_col = (uint32_t)(((lane >> 3) & 1) * 16);

    float part_acc[2][2];
#pragma unroll
    for (int mt = 0; mt < 2; mt++) { part_acc[mt][0] = 0.f; part_acc[mt][1] = 0.f; }

    float accG1[2][4][4];
    uint32_t accG2[2][4][2], accG3[2][4][2];
#pragma unroll
    for (int mt = 0; mt < 2; mt++)
#pragma unroll
        for (int nt = 0; nt < 4; nt++) {
#pragma unroll
            for (int e = 0; e < 4; e++) accG1[mt][nt][e] = 0.f;
            accG2[mt][nt][0] = 0u; accG2[mt][nt][1] = 0u;
            accG3[mt][nt][0] = 0u; accG3[mt][nt][1] = 0u;
        }

    fill_stage(smem_base, 0, i0, NT_a, n0a, n0b, s_off, tid); cp_commit();
    fill_stage(smem_base, 1, i0, NT_a, n0a, n0b, s_off, tid); cp_commit();

    for (int t = 0; t < NTT; ++t) {
        if (t + 1 < NTT) cp_wait1(); else cp_wait0();
        __syncthreads();

        const uint32_t sb = smem_base + (uint32_t)((t % NSTAGE) * STAGE_B);
#pragma unroll
        for (int k16 = 0; k16 < 2; k16++) {
            const uint32_t kofs = (uint32_t)(k16 * 32);
            uint32_t ah[2][4], al[2][4];
#pragma unroll
            for (int mt = 0; mt < 2; mt++) {
                ldsm4(ah[mt], sb + OFF_H + a_off + mt * 16 * ROWB + kofs);
                ldsm4(al[mt], sb + OFF_L + a_off + mt * 16 * ROWB + kofs);
            }
            uint32_t bh[4][2], bl[4][2];
#pragma unroll
            for (int u = 0; u < 2; u++) {
                uint32_t r4[4];
                ldsm4(r4, sb + OFF_VH + (b_row + u * 16) * ROWB + b_col + kofs);
                bh[2 * u][0] = r4[0]; bh[2 * u][1] = r4[1];
                bh[2 * u + 1][0] = r4[2]; bh[2 * u + 1][1] = r4[3];
                ldsm4(r4, sb + OFF_VL + (b_row + u * 16) * ROWB + b_col + kofs);
                bl[2 * u][0] = r4[0]; bl[2 * u][1] = r4[1];
                bl[2 * u + 1][0] = r4[2]; bl[2 * u + 1][1] = r4[3];
            }
#pragma unroll
            for (int mt = 0; mt < 2; mt++)
#pragma unroll
                for (int nt = 0; nt < 4; nt++)
                    mma16816(accG1[mt][nt], ah[mt], bh[nt]);
#pragma unroll
            for (int mt = 0; mt < 2; mt++)
#pragma unroll
                for (int nt = 0; nt < 4; nt++)
                    mma16816h(accG2[mt][nt], ah[mt], bl[nt]);
#pragma unroll
            for (int mt = 0; mt < 2; mt++)
#pragma unroll
                for (int nt = 0; nt < 4; nt++)
                    mma16816h(accG3[mt][nt], al[mt], bh[nt]);
        }
        if (t + 2 < NTT) {
            fill_stage(smem_base, t + 2, i0, NT_a, n0a, n0b, s_off, tid);
            cp_commit();
        }

        if (t == NT_a - 1 || t == NTT - 1) {
            // epilogue for this k-block: part += sum_k (G1+G2+G3)*op; clear accs
            const int n0 = (t == NT_a - 1) ? n0a : n0b;
#pragma unroll
            for (int mt = 0; mt < 2; mt++)
#pragma unroll
                for (int ir = 0; ir < 2; ir++) {
                    const int i_g = i0 + mw * 32 + mt * 16 + (lane >> 2) + ir * 8;
                    const size_t base = (size_t)i_g * H + n0 + nw * 32 + (lane & 3) * 2;
                    float s = 0.f;
#pragma unroll
                    for (int nt = 0; nt < 4; nt++) {
                        float2 w2 = *reinterpret_cast<const float2*>(op + base + nt * 8);
                        float2 g2 = __half22float2(*reinterpret_cast<__half2*>(&accG2[mt][nt][ir]));
                        float2 g3 = __half22float2(*reinterpret_cast<__half2*>(&accG3[mt][nt][ir]));
                        s += (accG1[mt][nt][ir * 2 + 0] + g2.x + g3.x) * w2.x
                           + (accG1[mt][nt][ir * 2 + 1] + g2.y + g3.y) * w2.y;
                    }
                    part_acc[mt][ir] += s;
#pragma unroll
                    for (int nt = 0; nt < 4; nt++) {
                        accG1[mt][nt][ir * 2 + 0] = 0.f; accG1[mt][nt][ir * 2 + 1] = 0.f;
                        accG2[mt][nt][ir] = 0u;
                        accG3[mt][nt][ir] = 0u;
                    }
                }
        }
    }

    // reduce 4 lanes sharing i, combine 2 nw warps via smem, one atomicAdd per i
#pragma unroll
    for (int mt = 0; mt < 2; mt++)
#pragma unroll
        for (int ir = 0; ir < 2; ir++) {
            float v = part_acc[mt][ir];
            v += __shfl_xor_sync(0xffffffffu, v, 1);
            v += __shfl_xor_sync(0xffffffffu, v, 2);
            part_acc[mt][ir] = v;
        }
    float* sp = reinterpret_cast<float*>(smem + OFF_SP);
    if ((lane & 3) == 0) {
#pragma unroll
        for (int mt = 0; mt < 2; mt++)
#pragma unroll
            for (int ir = 0; ir < 2; ir++) {
                int i_loc = mw * 32 + mt * 16 + (lane >> 2) + ir * 8;
                sp[nw * 128 + i_loc] = part_acc[mt][ir];
            }
    }
    __syncthreads();
    for (int i = tid; i < TM; i += NTHREADS)
        atomicAdd(&g_logits[b * H + i0 + i], 2.0f * (sp[i] + sp[128 + i]));
}

// ---------------- softmax ----------------
__global__ void Measurement_68307159875839_softmax(float* __restrict__ out) {
    __shared__ float red[NTHREADS / 32];
    const int b = blockIdx.x, tid = threadIdx.x;
    const float* row = g_logits + b * H;
    float m = -1e30f;
    for (int i = tid; i < H; i += NTHREADS) m = fmaxf(m, row[i]);
#pragma unroll
    for (int o = 16; o > 0; o >>= 1) m = fmaxf(m, __shfl_xor_sync(0xffffffffu, m, o));
    if ((tid & 31) == 0) red[tid >> 5] = m;
    __syncthreads();
    m = red[0];
#pragma unroll
    for (int wv = 1; wv < NTHREADS / 32; wv++) m = fmaxf(m, red[wv]);
    __syncthreads();
    float s = 0.0f;
    for (int i = tid; i < H; i += NTHREADS) s += __expf(row[i] - m);
#pragma unroll
    for (int o = 16; o > 0; o >>= 1) s += __shfl_xor_sync(0xffffffffu, s, o);
    if ((tid & 31) == 0) red[tid >> 5] = s;
    __syncthreads();
    s = 0.0f;
#pragma unroll
    for (int wv = 0; wv < NTHREADS / 32; wv++) s += red[wv];
    const float inv = 1.0f / s;
    for (int i = tid; i < H; i += NTHREADS) out[b * H + i] = __expf(row[i] - m) * inv;
}

extern "C" void kernel_launch(void* const* d_in, const int* in_sizes, int n_in,
                              void* d_out, int out_size) {
    const float* inputs = (const float*)d_in[0];   // [128, 768, 768] fp32
    const float* op     = (const float*)d_in[1];   // [768, 768] fp32
    float* out = (float*)d_out;                    // [128, 768] fp32

    static int configured = 0;
    static cudaStream_t s2;
    static cudaEvent_t evFork;
    static cudaEvent_t evSym[NCHUNK];
    if (!configured) {
        cudaFuncSetAttribute(Measurement_68307159875839_gemm,
                             cudaFuncAttributeMaxDynamicSharedMemorySize, SMEM_TOTAL);
        cudaStreamCreateWithFlags(&s2, cudaStreamNonBlocking);
        cudaEventCreateWithFlags(&evFork, cudaEventDisableTiming);
        for (int c = 0; c < NCHUNK; c++)
            cudaEventCreateWithFlags(&evSym[c], cudaEventDisableTiming);
        configured = 1;
    }
    __half *op_hi, *op_lo;
    cudaGetSymbolAddress((void**)&op_hi, g_op_hi);
    cudaGetSymbolAddress((void**)&op_lo, g_op_lo);

    cudaEventRecord(evFork, 0);
    cudaStreamWaitEvent(s2, evFork, 0);

    const int n4_op = H * H / 4;
    Measurement_68307159875839_cvt<<<(n4_op + 255) / 256, 256>>>(op, op_hi, op_lo, n4_op);

    for (int c = 0; c < NCHUNK; c++) {
        Measurement_68307159875839_sym<<<dim3(H / 32, H / 32, CHUNK_B), 256, 0, s2>>>(
            inputs, c * CHUNK_B);
        cudaEventRecord(evSym[c], s2);
    }
    for (int c = 0; c < NCHUNK; c++) {
        cudaStreamWaitEvent(0, evSym[c], 0);
        Measurement_68307159875839_gemm<<<dim3(NXB, CHUNK_B), NTHREADS, SMEM_TOTAL>>>(
            op, c * CHUNK_B);
    }
    Measurement_68307159875839_softmax<<<BATCHN, NTHREADS>>>(out);
}

// round 13
// speedup vs baseline: 1.4911x; 1.0177x over previous
#include <cuda_runtime.h>
#include <cuda_fp16.h>
#include <cstdint>
#include <cmath>

#define H 768
#define BATCHN 128
#define NCHUNK 8
#define CHUNK_B (BATCHN / NCHUNK)   // 16
#define TM 128
#define TNO 64
#define TKC 32
#define NPAIR 6                  // ct pairs (p, 11-p), 26 steps each
#define NXB (6 * NPAIR)          // 36 tasks per batch
#define NTT 26
#define NTHREADS 256
#define NSYMT 312                // 300 triangular tiles + 12 zero tiles

// SMEM per stage: h 128 rows + l 128 rows + Vh 64 + Vl 64; 80B pitch
#define ROWB 80
#define OFF_H  0
#define OFF_L  (128 * ROWB)               // 10240
#define OFF_VH (256 * ROWB)               // 20480
#define OFF_VL (320 * ROWB)               // 25600
#define STAGE_B (384 * ROWB)              // 30720
#define NSTAGE 3
#define OFF_SP (NSTAGE * STAGE_B)         // 92160; partials 2*128 floats
#define SMEM_TOTAL (OFF_SP + 2 * 128 * 4) // 93184 -> 2 CTAs/SM

__device__ float g_logits[BATCHN * H];
__device__ __half g_sh[(size_t)BATCHN * H * H];   // V hi (lower tri, half diag)
__device__ __half g_sl[(size_t)BATCHN * H * H];   // V lo
__device__ __half g_op_hi[H * H];
__device__ __half g_op_lo[H * H];

// ---------------- helpers ----------------
__device__ __forceinline__ uint32_t smem_u32(const void* p) {
    uint32_t a;
    asm("{ .reg .u64 t; cvta.to.shared.u64 t, %1; cvt.u32.u64 %0, t; }" : "=r"(a) : "l"(p));
    return a;
}
__device__ __forceinline__ void ldsm4(uint32_t* r, uint32_t addr) {
    asm volatile("ldmatrix.sync.aligned.m8n8.x4.shared.b16 {%0,%1,%2,%3}, [%4];"
                 : "=r"(r[0]), "=r"(r[1]), "=r"(r[2]), "=r"(r[3]) : "r"(addr));
}
__device__ __forceinline__ void mma16816(float* d, const uint32_t* a, const uint32_t* b) {
    asm volatile(
        "mma.sync.aligned.m16n8k16.row.col.f32.f16.f16.f32 "
        "{%0,%1,%2,%3}, {%4,%5,%6,%7}, {%8,%9}, {%0,%1,%2,%3};"
        : "+f"(d[0]), "+f"(d[1]), "+f"(d[2]), "+f"(d[3])
        : "r"(a[0]), "r"(a[1]), "r"(a[2]), "r"(a[3]), "r"(b[0]), "r"(b[1]));
}
__device__ __forceinline__ void mma16816h(uint32_t* d, const uint32_t* a, const uint32_t* b) {
    asm volatile(
        "mma.sync.aligned.m16n8k16.row.col.f16.f16.f16.f16 "
        "{%0,%1}, {%2,%3,%4,%5}, {%6,%7}, {%0,%1};"
        : "+r"(d[0]), "+r"(d[1])
        : "r"(a[0]), "r"(a[1]), "r"(a[2]), "r"(a[3]), "r"(b[0]), "r"(b[1]));
}
__device__ __forceinline__ void cp16(uint32_t dst, const void* src) {
    asm volatile("cp.async.cg.shared.global [%0], [%1], 16;" :: "r"(dst), "l"(src));
}
__device__ __forceinline__ void cp_commit() { asm volatile("cp.async.commit_group;" ::: "memory"); }
__device__ __forceinline__ void cp_wait1()  { asm volatile("cp.async.wait_group 1;" ::: "memory"); }
__device__ __forceinline__ void cp_wait0()  { asm volatile("cp.async.wait_group 0;" ::: "memory"); }
__device__ __forceinline__ uint32_t pack2(__half a, __half b) {
    __half2 h = __halves2half2(a, b);
    return *reinterpret_cast<uint32_t*>(&h);
}
__device__ __forceinline__ void split2(float s0, float s1, uint32_t& hi, uint32_t& lo) {
    __half h0 = __float2half_rn(s0), h1 = __float2half_rn(s1);
    __half l0 = __float2half_rn(s0 - __half2float(h0));
    __half l1 = __float2half_rn(s1 - __half2float(h1));
    hi = pack2(h0, h1);
    lo = pack2(l0, l1);
}

// -------- sym: V[k,j] = sym(A)[k,j] j<k, V[k,k]=A[k,k]/2, zero above; plus the
//          12 zero tiles (Rt even, Ct=Rt+1) read by the 64-wide k-blocks. ------
// grid (NSYMT, CHUNK_B): x = linear tile id (300 triangular, then 12 zero).
__global__ void __launch_bounds__(256)
Measurement_68307159875839_sym(const float* __restrict__ A, int b0) {
    const int tlin = blockIdx.x;
    const int b = b0 + blockIdx.y;
    __half* vh = g_sh + (size_t)b * H * H;
    __half* vl = g_sl + (size_t)b * H * H;
    const int t = threadIdx.x;
    const int r16 = t >> 4, cp = t & 15;

    int Rt, Ct;
    if (tlin >= 300) {                 // zero tile
        const int z = tlin - 300;
        Rt = 2 * z; Ct = Rt + 1;
        const int k0 = Rt * 32, j0 = Ct * 32;
#pragma unroll
        for (int rr = 0; rr < 2; rr++) {
            size_t off = (size_t)(k0 + rr * 16 + r16) * H + j0 + 2 * cp;
            *reinterpret_cast<uint32_t*>(vh + off) = 0u;
            *reinterpret_cast<uint32_t*>(vl + off) = 0u;
        }
        return;
    }
    Rt = (int)((sqrtf(8.f * tlin + 1.f) - 1.f) * 0.5f);
    while ((Rt + 1) * (Rt + 2) / 2 <= tlin) Rt++;
    while (Rt * (Rt + 1) / 2 > tlin) Rt--;
    Ct = tlin - Rt * (Rt + 1) / 2;

    __shared__ float sKJ[32][33], sJK[32][33];
    const float* Ab = A + (size_t)b * H * H;
    const int k0 = Rt * 32, j0 = Ct * 32;
    {
        const int r = t >> 3, q = t & 7;
        float4 va = *reinterpret_cast<const float4*>(Ab + (size_t)(k0 + r) * H + j0 + q * 4);
        sKJ[r][q * 4 + 0] = va.x; sKJ[r][q * 4 + 1] = va.y;
        sKJ[r][q * 4 + 2] = va.z; sKJ[r][q * 4 + 3] = va.w;
        float4 vb = *reinterpret_cast<const float4*>(Ab + (size_t)(j0 + r) * H + k0 + q * 4);
        sJK[r][q * 4 + 0] = vb.x; sJK[r][q * 4 + 1] = vb.y;
        sJK[r][q * 4 + 2] = vb.z; sJK[r][q * 4 + 3] = vb.w;
    }
    __syncthreads();
#pragma unroll
    for (int rr = 0; rr < 2; rr++) {
        const int row = rr * 16 + r16;                 // k within tile
        const int c0 = 2 * cp, c1 = 2 * cp + 1;        // j within tile
        float v0 = 0.5f * (sKJ[row][c0] + sJK[c0][row]);
        float v1 = 0.5f * (sKJ[row][c1] + sJK[c1][row]);
        if (Rt == Ct) {
            v0 = (c0 < row) ? v0 : ((c0 == row) ? 0.5f * v0 : 0.f);
            v1 = (c1 < row) ? v1 : ((c1 == row) ? 0.5f * v1 : 0.f);
        }
        uint32_t hi, lo;
        split2(v0, v1, hi, lo);
        size_t off = (size_t)(k0 + row) * H + j0 + c0;
        *reinterpret_cast<uint32_t*>(vh + off) = hi;
        *reinterpret_cast<uint32_t*>(vl + off) = lo;
    }
}

// ---------------- cvt: op fp32 -> fp16 hi/lo, + zero logits ----------------
__global__ void Measurement_68307159875839_cvt(const float* __restrict__ src,
                                               __half* __restrict__ dst_hi,
                                               __half* __restrict__ dst_lo, int n4) {
    int idx = blockIdx.x * blockDim.x + threadIdx.x;
    if (idx < BATCHN * H) g_logits[idx] = 0.0f;
    if (idx >= n4) return;
    float4 v = reinterpret_cast<const float4*>(src)[idx];
    uint32_t h0, l0, h1, l1;
    split2(v.x, v.y, h0, l0);
    split2(v.z, v.w, h1, l1);
    reinterpret_cast<uint2*>(dst_hi)[idx] = make_uint2(h0, h1);
    reinterpret_cast<uint2*>(dst_lo)[idx] = make_uint2(l0, l1);
}

// ---------------- block-triangular GEMM (3 products) + fused diag ----------------
__device__ __forceinline__ void fill_stage(uint32_t smem_base, int t, int i0,
                                           int NT_a, int n0a, int n0b,
                                           size_t s_off, int tid) {
    const int n0 = (t < NT_a) ? n0a : n0b;
    const int k0 = ((t < NT_a) ? t : (t - NT_a)) * TKC;
    const int s = t % NSTAGE;
#pragma unroll
    for (int r = 0; r < 6; r++) {
        int q = r * NTHREADS + tid;
        const __half* src;
        uint32_t off;
        if (q < 512) {
            int row = q >> 2, c = q & 3;
            off = OFF_H + row * ROWB + c * 16;
            src = g_op_hi + (size_t)(i0 + row) * H + k0 + c * 8;
        } else if (q < 1024) {
            int q2 = q - 512, row = q2 >> 2, c = q2 & 3;
            off = OFF_L + row * ROWB + c * 16;
            src = g_op_lo + (size_t)(i0 + row) * H + k0 + c * 8;
        } else if (q < 1280) {
            int q2 = q - 1024, row = q2 >> 2, c = q2 & 3;
            off = OFF_VH + row * ROWB + c * 16;
            src = g_sh + s_off + (size_t)(n0 + row) * H + k0 + c * 8;
        } else {
            int q2 = q - 1280, row = q2 >> 2, c = q2 & 3;
            off = OFF_VL + row * ROWB + c * 16;
            src = g_sl + s_off + (size_t)(n0 + row) * H + k0 + c * 8;
        }
        cp16(smem_base + (uint32_t)(s * STAGE_B) + off, src);
    }
}

// grid: (36, CHUNK_B); x = i-tile (6) x pair (6); 26 steps per CTA.
__global__ void __launch_bounds__(NTHREADS, 2)
Measurement_68307159875839_gemm(const float* __restrict__ op, int b0) {
    extern __shared__ __align__(16) char smem[];
    const uint32_t smem_base = smem_u32(smem);
    const int tid = threadIdx.x;
    const int lane = tid & 31;
    const int w = tid >> 5;
    const int mw = w >> 1;          // 4 M-warps: 32 rows
    const int nw = w & 1;           // 2 N-warps: 32 cols
    const int i0 = (blockIdx.x % 6) * TM;
    const int p = blockIdx.x / 6;
    const int ct_a = p, ct_b = 11 - p;
    const int NT_a = 2 * (ct_a + 1);
    const int n0a = ct_a * TNO, n0b = ct_b * TNO;
    const int b = b0 + blockIdx.y;
    const size_t s_off = (size_t)b * H * H;

    const uint32_t a_off = (uint32_t)((mw * 32 + (lane & 15)) * ROWB + (lane >> 4) * 16);
    const uint32_t b_row = (uint32_t)(nw * 32 + (lane & 7) + ((lane & 16) >> 1));
    const uint32_t b_col = (uint32_t)(((lane >> 3) & 1) * 16);

    float part_acc[2][2];
#pragma unroll
    for (int mt = 0; mt < 2; mt++) { part_acc[mt][0] = 0.f; part_acc[mt][1] = 0.f; }

    float accG1[2][4][4];
    uint32_t accG23[2][4][2];     // merged f16 correction acc (G2+G3)
#pragma unroll
    for (int mt = 0; mt < 2; mt++)
#pragma unroll
        for (int nt = 0; nt < 4; nt++) {
#pragma unroll
            for (int e = 0; e < 4; e++) accG1[mt][nt][e] = 0.f;
            accG23[mt][nt][0] = 0u; accG23[mt][nt][1] = 0u;
        }

    fill_stage(smem_base, 0, i0, NT_a, n0a, n0b, s_off, tid); cp_commit();
    fill_stage(smem_base, 1, i0, NT_a, n0a, n0b, s_off, tid); cp_commit();

    for (int t = 0; t < NTT; ++t) {
        if (t + 1 < NTT) cp_wait1(); else cp_wait0();
        __syncthreads();

        const uint32_t sb = smem_base + (uint32_t)((t % NSTAGE) * STAGE_B);
#pragma unroll
        for (int k16 = 0; k16 < 2; k16++) {
            const uint32_t kofs = (uint32_t)(k16 * 32);
            uint32_t ah[2][4], al[2][4];
#pragma unroll
            for (int mt = 0; mt < 2; mt++) {
                ldsm4(ah[mt], sb + OFF_H + a_off + mt * 16 * ROWB + kofs);
                ldsm4(al[mt], sb + OFF_L + a_off + mt * 16 * ROWB + kofs);
            }
            uint32_t bh[4][2], bl[4][2];
#pragma unroll
            for (int u = 0; u < 2; u++) {
                uint32_t r4[4];
                ldsm4(r4, sb + OFF_VH + (b_row + u * 16) * ROWB + b_col + kofs);
                bh[2 * u][0] = r4[0]; bh[2 * u][1] = r4[1];
                bh[2 * u + 1][0] = r4[2]; bh[2 * u + 1][1] = r4[3];
                ldsm4(r4, sb + OFF_VL + (b_row + u * 16) * ROWB + b_col + kofs);
                bl[2 * u][0] = r4[0]; bl[2 * u][1] = r4[1];
                bl[2 * u + 1][0] = r4[2]; bl[2 * u + 1][1] = r4[3];
            }
#pragma unroll
            for (int mt = 0; mt < 2; mt++)
#pragma unroll
                for (int nt = 0; nt < 4; nt++)
                    mma16816(accG1[mt][nt], ah[mt], bh[nt]);
#pragma unroll
            for (int mt = 0; mt < 2; mt++)
#pragma unroll
                for (int nt = 0; nt < 4; nt++)
                    mma16816h(accG23[mt][nt], ah[mt], bl[nt]);
#pragma unroll
            for (int mt = 0; mt < 2; mt++)
#pragma unroll
                for (int nt = 0; nt < 4; nt++)
                    mma16816h(accG23[mt][nt], al[mt], bh[nt]);
        }
        if (t + 2 < NTT) {
            fill_stage(smem_base, t + 2, i0, NT_a, n0a, n0b, s_off, tid);
            cp_commit();
        }

        if (t == NT_a - 1 || t == NTT - 1) {
            const int n0 = (t == NT_a - 1) ? n0a : n0b;
#pragma unroll
            for (int mt = 0; mt < 2; mt++)
#pragma unroll
                for (int ir = 0; ir < 2; ir++) {
                    const int i_g = i0 + mw * 32 + mt * 16 + (lane >> 2) + ir * 8;
                    const size_t base = (size_t)i_g * H + n0 + nw * 32 + (lane & 3) * 2;
                    float s = 0.f;
#pragma unroll
                    for (int nt = 0; nt < 4; nt++) {
                        float2 w2 = *reinterpret_cast<const float2*>(op + base + nt * 8);
                        float2 g23 = __half22float2(
                            *reinterpret_cast<__half2*>(&accG23[mt][nt][ir]));
                        s += (accG1[mt][nt][ir * 2 + 0] + g23.x) * w2.x
                           + (accG1[mt][nt][ir * 2 + 1] + g23.y) * w2.y;
                    }
                    part_acc[mt][ir] += s;
#pragma unroll
                    for (int nt = 0; nt < 4; nt++) {
                        accG1[mt][nt][ir * 2 + 0] = 0.f; accG1[mt][nt][ir * 2 + 1] = 0.f;
                        accG23[mt][nt][ir] = 0u;
                    }
                }
        }
    }

    // reduce 4 lanes sharing i, combine 2 nw warps via smem, one atomicAdd per i
#pragma unroll
    for (int mt = 0; mt < 2; mt++)
#pragma unroll
        for (int ir = 0; ir < 2; ir++) {
            float v = part_acc[mt][ir];
            v += __shfl_xor_sync(0xffffffffu, v, 1);
            v += __shfl_xor_sync(0xffffffffu, v, 2);
            part_acc[mt][ir] = v;
        }
    float* sp = reinterpret_cast<float*>(smem + OFF_SP);
    if ((lane & 3) == 0) {
#pragma unroll
        for (int mt = 0; mt < 2; mt++)
#pragma unroll
            for (int ir = 0; ir < 2; ir++) {
                int i_loc = mw * 32 + mt * 16 + (lane >> 2) + ir * 8;
                sp[nw * 128 + i_loc] = part_acc[mt][ir];
            }
    }
    __syncthreads();
    for (int i = tid; i < TM; i += NTHREADS)
        atomicAdd(&g_logits[b * H + i0 + i], 2.0f * (sp[i] + sp[128 + i]));
}

// ---------------- softmax ----------------
__global__ void Measurement_68307159875839_softmax(float* __restrict__ out) {
    __shared__ float red[NTHREADS / 32];
    const int b = blockIdx.x, tid = threadIdx.x;
    const float* row = g_logits + b * H;
    float m = -1e30f;
    for (int i = tid; i < H; i += NTHREADS) m = fmaxf(m, row[i]);
#pragma unroll
    for (int o = 16; o > 0; o >>= 1) m = fmaxf(m, __shfl_xor_sync(0xffffffffu, m, o));
    if ((tid & 31) == 0) red[tid >> 5] = m;
    __syncthreads();
    m = red[0];
#pragma unroll
    for (int wv = 1; wv < NTHREADS / 32; wv++) m = fmaxf(m, red[wv]);
    __syncthreads();
    float s = 0.0f;
    for (int i = tid; i < H; i += NTHREADS) s += __expf(row[i] - m);
#pragma unroll
    for (int o = 16; o > 0; o >>= 1) s += __shfl_xor_sync(0xffffffffu, s, o);
    if ((tid & 31) == 0) red[tid >> 5] = s;
    __syncthreads();
    s = 0.0f;
#pragma unroll
    for (int wv = 0; wv < NTHREADS / 32; wv++) s += red[wv];
    const float inv = 1.0f / s;
    for (int i = tid; i < H; i += NTHREADS) out[b * H + i] = __expf(row[i] - m) * inv;
}

extern "C" void kernel_launch(void* const* d_in, const int* in_sizes, int n_in,
                              void* d_out, int out_size) {
    const float* inputs = (const float*)d_in[0];   // [128, 768, 768] fp32
    const float* op     = (const float*)d_in[1];   // [768, 768] fp32
    float* out = (float*)d_out;                    // [128, 768] fp32

    static int configured = 0;
    static cudaStream_t s2, s3;
    static cudaEvent_t evFork, evCvt, evG3;
    static cudaEvent_t evSym[NCHUNK];
    if (!configured) {
        cudaFuncSetAttribute(Measurement_68307159875839_gemm,
                             cudaFuncAttributeMaxDynamicSharedMemorySize, SMEM_TOTAL);
        cudaStreamCreateWithFlags(&s2, cudaStreamNonBlocking);
        cudaStreamCreateWithFlags(&s3, cudaStreamNonBlocking);
        cudaEventCreateWithFlags(&evFork, cudaEventDisableTiming);
        cudaEventCreateWithFlags(&evCvt, cudaEventDisableTiming);
        cudaEventCreateWithFlags(&evG3, cudaEventDisableTiming);
        for (int c = 0; c < NCHUNK; c++)
            cudaEventCreateWithFlags(&evSym[c], cudaEventDisableTiming);
        configured = 1;
    }
    __half *op_hi, *op_lo;
    cudaGetSymbolAddress((void**)&op_hi, g_op_hi);
    cudaGetSymbolAddress((void**)&op_lo, g_op_lo);

    cudaEventRecord(evFork, 0);
    cudaStreamWaitEvent(s2, evFork, 0);

    const int n4_op = H * H / 4;
    Measurement_68307159875839_cvt<<<(n4_op + 255) / 256, 256>>>(op, op_hi, op_lo, n4_op);
    cudaEventRecord(evCvt, 0);
    cudaStreamWaitEvent(s3, evCvt, 0);

    for (int c = 0; c < NCHUNK; c++) {
        Measurement_68307159875839_sym<<<dim3(NSYMT, CHUNK_B), 256, 0, s2>>>(
            inputs, c * CHUNK_B);
        cudaEventRecord(evSym[c], s2);
    }
    // alternate gemm chunks across two streams so launch tails overlap
    for (int c = 0; c < NCHUNK; c++) {
        cudaStream_t gs = (c & 1) ? s3 : (cudaStream_t)0;
        cudaStreamWaitEvent(gs, evSym[c], 0);
        Measurement_68307159875839_gemm<<<dim3(NXB, CHUNK_B), NTHREADS, SMEM_TOTAL, gs>>>(
            op, c * CHUNK_B);
    }
    cudaEventRecord(evG3, s3);
    cudaStreamWaitEvent(0, evG3, 0);
    Measurement_68307159875839_softmax<<<BATCHN, NTHREADS>>>(out);
}